// round 11
// baseline (speedup 1.0000x reference)
#include <cuda_runtime.h>
#include <cuda_bf16.h>
#include <math_constants.h>
#include <cstdint>

// Problem constants (fixed by setup_inputs)
#define NN 100000
#define EE 1600000
#define DEG 16
#define HID 64
#define NLAYERS 6
#define TILES 10          // tiles (of 8 nodes) per edge block
#define GTILES 6          // tiles (of 64 nodes) per gemm2 block

// ---------------------------------------------------------------------------
// Device scratch (no allocation allowed)
__device__ __align__(128) float g_A[NN * HID];
__device__ __align__(128) float g_B[NN * HID];
__device__ __align__(128) float g_h0[NN * HID];
__device__ __align__(128) float g_h1[NN * HID];
__device__ __align__(128) int   g_src[EE];
__device__ __align__(128) uint4 g_W2F[7 * 1024];   // edge W2 frags, per layer
__device__ __align__(128) uint4 g_WcF[7 * 2048];   // node Wc frags, per layer
__device__ int g_is64;

// ---------------------------------------------------------------------------
// Warp-MMA helpers (sm_80+/sm_90 instructions; target is plain sm_100)
__device__ __forceinline__ uint32_t smem_u32(const void* p) {
    uint32_t a;
    asm("{ .reg .u64 t; cvta.to.shared.u64 t, %1; cvt.u32.u64 %0, t; }"
        : "=r"(a) : "l"(p));
    return a;
}

__device__ __forceinline__ void mma_bf16(float* d, const uint32_t* a,
                                         uint32_t b0, uint32_t b1) {
    asm volatile(
        "mma.sync.aligned.m16n8k16.row.col.f32.bf16.bf16.f32 "
        "{%0,%1,%2,%3}, {%4,%5,%6,%7}, {%8,%9}, {%0,%1,%2,%3};"
        : "+f"(d[0]), "+f"(d[1]), "+f"(d[2]), "+f"(d[3])
        : "r"(a[0]), "r"(a[1]), "r"(a[2]), "r"(a[3]), "r"(b0), "r"(b1));
}

__device__ __forceinline__ void ldsm4(uint32_t* r, uint32_t addr) {
    asm volatile(
        "ldmatrix.sync.aligned.m8n8.x4.shared.b16 {%0,%1,%2,%3}, [%4];"
        : "=r"(r[0]), "=r"(r[1]), "=r"(r[2]), "=r"(r[3]) : "r"(addr));
}

// Pack two f32 -> bf16x2 (lo half = v0, hi half = v1)
__device__ __forceinline__ uint32_t pack_bf16x2(float v0, float v1) {
    uint32_t r;
    asm("cvt.rn.bf16x2.f32 %0, %1, %2;" : "=r"(r) : "f"(v1), "f"(v0));
    return r;
}
__device__ __forceinline__ float bf16_hi_f(float v) {
    __nv_bfloat16 h = __float2bfloat16_rn(v);
    return __bfloat162float(h);
}
// Recover rounded fp32 values from a packed bf16x2 (lo elem / hi elem)
__device__ __forceinline__ float bf16x2_lo_f(uint32_t p) {
    return __uint_as_float(p << 16);
}
__device__ __forceinline__ float bf16x2_hi_f(uint32_t p) {
    return __uint_as_float(p & 0xFFFF0000u);
}

// ---------------------------------------------------------------------------
// Detect int64 vs int32 edge_index (JAX x64-off gives int32)
__global__ void k_detect(const int* __restrict__ ei32) {
    int flag = 1;
    for (int i = 0; i < 64; ++i)
        if (ei32[2 * i + 1] != 0) { flag = 0; break; }
    g_is64 = flag;
}

__global__ void k_src(const void* __restrict__ ei) {
    int e = blockIdx.x * blockDim.x + threadIdx.x;
    if (e >= EE) return;
    if (g_is64) g_src[e] = (int)((const long long*)ei)[e];
    else        g_src[e] = ((const int*)ei)[e];
}

// ---------------------------------------------------------------------------
// Input layer A/B:  A = x @ (Wi1[0:4]-Wi1[4:8]) + bi1,  B = x @ Wi1[4:8]
__global__ void k_input(const float* __restrict__ x,
                        const float* __restrict__ Wi1,
                        const float* __restrict__ bi1) {
    int gid = blockIdx.x * blockDim.x + threadIdx.x;
    if (gid >= NN * HID) return;
    int i = gid >> 6, t = gid & 63;
    float4 xv = ((const float4*)x)[i];
    float xa[4] = {xv.x, xv.y, xv.z, xv.w};
    float a = bi1[t], b = 0.f;
#pragma unroll
    for (int k = 0; k < 4; ++k) {
        float wt = Wi1[k * 64 + t];
        float wb = Wi1[(4 + k) * 64 + t];
        a += xa[k] * (wt - wb);
        b += xa[k] * wb;
    }
    g_A[gid] = a;
    g_B[gid] = b;
}

// ---------------------------------------------------------------------------
// ONE fused fragment-prep kernel for ALL layers.
__device__ __forceinline__ float wc_elem(const float* W1, int k, int c) {
    return (c < 64) ? W1[k * 64 + c] - W1[(64 + k) * 64 + c]
                    : W1[(64 + k) * 64 + (c - 64)];
}

__global__ void k_prepall(const float* __restrict__ Wi2,
                          const float* __restrict__ Wh2,
                          const float* __restrict__ Wh1,
                          const float* __restrict__ Wo1) {
    int idx = blockIdx.x * blockDim.x + threadIdx.x;
    if (idx < 7 * 1024) {
        int l = idx >> 10, id = idx & 1023;
        const float* W2 = (l == 0) ? Wi2 : Wh2 + (l - 1) * 4096;
        int fl = id & 31, frag = id >> 5;
        int ks = frag & 3, nt = frag >> 2;
        int kr = ks * 16 + 2 * (fl & 3);
        int nc = nt * 8 + (fl >> 2);
        float v00 = W2[kr * 64 + nc],       v01 = W2[(kr + 1) * 64 + nc];
        float v10 = W2[(kr + 8) * 64 + nc], v11 = W2[(kr + 9) * 64 + nc];
        float h00 = bf16_hi_f(v00), h01 = bf16_hi_f(v01);
        float h10 = bf16_hi_f(v10), h11 = bf16_hi_f(v11);
        uint4 o;
        o.x = pack_bf16x2(h00, h01);
        o.y = pack_bf16x2(h10, h11);
        o.z = pack_bf16x2(v00 - h00, v01 - h01);
        o.w = pack_bf16x2(v10 - h10, v11 - h11);
        g_W2F[idx] = o;
    } else {
        int j = idx - 7 * 1024;
        if (j >= 7 * 2048) return;
        int l = j >> 11, id = j & 2047;
        const float* W1 = (l < 6) ? Wh1 + l * 8192 : Wo1;
        int fl = id & 31, frag = id >> 5;
        int ks = frag & 3, nt = frag >> 2;                // nt 0..15
        int kr = ks * 16 + 2 * (fl & 3);
        int nc = nt * 8 + (fl >> 2);
        float v00 = wc_elem(W1, kr, nc),     v01 = wc_elem(W1, kr + 1, nc);
        float v10 = wc_elem(W1, kr + 8, nc), v11 = wc_elem(W1, kr + 9, nc);
        float h00 = bf16_hi_f(v00), h01 = bf16_hi_f(v01);
        float h10 = bf16_hi_f(v10), h11 = bf16_hi_f(v11);
        uint4 o;
        o.x = pack_bf16x2(h00, h01);
        o.y = pack_bf16x2(h10, h11);
        o.z = pack_bf16x2(v00 - h00, v01 - h01);
        o.w = pack_bf16x2(v10 - h10, v11 - h11);
        g_WcF[j] = o;
    }
}

// ---------------------------------------------------------------------------
// Node GEMM via mma (3xBF16): GTILES tiles of [A|B] (64 rows x 128 cols).
// Wc fragments staged ONCE per block (32 KB amortized over GTILES tiles).
// Warp-local H build (warp w owns rows [16w,16w+16)) -> no per-tile barrier.
#define GH_HI 0u
#define GH_LO 9216u
#define GWF   18432u
#define GEMM_SMEM 51200

__global__ __launch_bounds__(128, 4) void k_gemm2(int insel, int lsel,
                                                  const float* __restrict__ b1) {
    extern __shared__ __align__(128) char smem[];
    uint32_t sb = smem_u32(smem);
    int tid = threadIdx.x, w = tid >> 5, lane = tid & 31;
    const float* hin = insel ? g_h1 : g_h0;
    const uint4* wsrc = g_WcF + lsel * 2048;

    // stage Wc fragments (32 KB) -- the ONLY block-wide sync
#pragma unroll
    for (int i = 0; i < 16; ++i)
        *(uint4*)(smem + GWF + (size_t)(i * 128 + tid) * 16) =
            wsrc[i * 128 + tid];
    __syncthreads();

    uint32_t abase = sb + (uint32_t)(w * 16 + (lane & 15)) * 144
                        + (uint32_t)(lane >> 4) * 16;

#pragma unroll 1
    for (int t = 0; t < GTILES; ++t) {
        int base = (blockIdx.x * GTILES + t) * 64;
        if (base >= NN) break;

        // Warp-local H build: warp w rows [16w, 16w+16), 16 f4-cols each
#pragma unroll
        for (int i = 0; i < 8; ++i) {
            int r = w * 16 + 2 * i + (lane >> 4);
            int f = lane & 15;
            int nl = base + r; if (nl >= NN) nl = NN - 1;
            float4 hv = __ldg(&((const float4*)hin)[nl * 16 + f]);
            uint32_t hp0 = pack_bf16x2(hv.x, hv.y);
            uint32_t hp1 = pack_bf16x2(hv.z, hv.w);
            float e0 = bf16x2_lo_f(hp0), e1 = bf16x2_hi_f(hp0);
            float e2 = bf16x2_lo_f(hp1), e3 = bf16x2_hi_f(hp1);
            uint2 hi = {hp0, hp1};
            uint2 lo = {pack_bf16x2(hv.x - e0, hv.y - e1),
                        pack_bf16x2(hv.z - e2, hv.w - e3)};
            *(uint2*)(smem + GH_HI + (size_t)r * 144 + (size_t)f * 8) = hi;
            *(uint2*)(smem + GH_LO + (size_t)r * 144 + (size_t)f * 8) = lo;
        }
        __syncwarp();

        float acc[16][4] = {};
#pragma unroll
        for (int ks = 0; ks < 4; ++ks) {
            uint32_t Ah[4], Al[4];
            ldsm4(Ah, abase + GH_HI + ks * 32);
            ldsm4(Al, abase + GH_LO + ks * 32);
#pragma unroll
            for (int half = 0; half < 2; ++half) {
                uint4 wf[8];
#pragma unroll
                for (int q = 0; q < 8; ++q) {
                    int nt = half * 8 + q;
                    wf[q] = *(const uint4*)(smem + GWF + ((nt * 4 + ks) * 32 + lane) * 16);
                }
#pragma unroll
                for (int q = 0; q < 8; ++q)
                    mma_bf16(acc[half * 8 + q], Ah, wf[q].x, wf[q].y);
#pragma unroll
                for (int q = 0; q < 8; ++q)
                    mma_bf16(acc[half * 8 + q], Al, wf[q].x, wf[q].y);
#pragma unroll
                for (int q = 0; q < 8; ++q)
                    mma_bf16(acc[half * 8 + q], Ah, wf[q].z, wf[q].w);
            }
        }

        // Epilogue
        int r0 = base + w * 16 + (lane >> 2);
#pragma unroll
        for (int nt = 0; nt < 16; ++nt) {
            int col = nt * 8 + (lane & 3) * 2;
#pragma unroll
            for (int hf = 0; hf < 2; ++hf) {
                int node = r0 + hf * 8;
                if (node < NN) {
                    float vx = acc[nt][2 * hf], vy = acc[nt][2 * hf + 1];
                    if (col < 64) {
                        vx += __ldg(&b1[col]); vy += __ldg(&b1[col + 1]);
                        *(float2*)(g_A + node * 64 + col) = make_float2(vx, vy);
                    } else {
                        *(float2*)(g_B + node * 64 + col - 64) = make_float2(vx, vy);
                    }
                }
            }
        }
        __syncwarp();   // H reuse safety before next tile's build
    }
}

// ---------------------------------------------------------------------------
// Edge kernel: bf16 mma m16n8k16 (3xBF16), barrier-free multi-tile pipeline.
// Block = 128 thr / 4 warps; TILES tiles of 8 nodes (128 edge rows) each.
// Build-phase LDG minimized: A operand hoisted to 2 registers per tile
// (only 2 distinct (node,f) pairs per thread), src indices via 1 LDG + shfl.
#define H_HI  0u
#define H_LO  18432u
#define WF    36864u
#define EDGE_SMEM 53248

__global__ __launch_bounds__(128, 4) void k_edge_mma(int lsel,
                                                     const float* __restrict__ b2,
                                                     int outsel) {
    extern __shared__ __align__(128) char smem[];
    uint32_t sb = smem_u32(smem);
    int tid = threadIdx.x, w = tid >> 5, lane = tid & 31;
    const uint4* wsrc = g_W2F + lsel * 1024;
    float* outp = (outsel ? g_h1 : g_h0);

    // stage W2 fragments (16 KB) -- the only block-wide sync
#pragma unroll
    for (int i = 0; i < 8; ++i)
        *(uint4*)(smem + WF + (size_t)(i * 128 + tid) * 16) =
            wsrc[i * 128 + tid];
    __syncthreads();

    uint32_t a_row = (uint32_t)((lane & 15) * 144 + (lane >> 4) * 16);
    uint32_t a0base = sb + (uint32_t)(w * 32) * 144 + a_row;
    uint32_t a1base = a0base + 16 * 144;
    int f = lane & 15;

#pragma unroll 1
    for (int t = 0; t < TILES; ++t) {
        int tile = blockIdx.x * TILES + t;
        int base_node = tile * 8;

        // One LDG covers all 32 src indices for this warp's rows
        int s_all = __ldg(&g_src[tile * 128 + w * 32 + lane]);
        // A operand: only 2 distinct values per thread (node 2w / 2w+1, col f)
        float4 av0 = __ldg(&((const float4*)g_A)[(base_node + 2 * w) * 16 + f]);
        float4 av1 = __ldg(&((const float4*)g_A)[(base_node + 2 * w + 1) * 16 + f]);

        // H1 build (warp-private rows): h = relu(A + B[src]) hi/lo bf16
#pragma unroll
        for (int i = 0; i < 16; ++i) {
            int r = w * 32 + 2 * i + (lane >> 4);
            int src = __shfl_sync(0xffffffffu, s_all, 2 * i + (lane >> 4));
            float4 bv = __ldg(&((const float4*)g_B)[src * 16 + f]);
            float4 av = (i < 8) ? av0 : av1;          // node_l = 2w + (i>>3)
            float h0 = fmaxf(av.x + bv.x, 0.f);
            float h1 = fmaxf(av.y + bv.y, 0.f);
            float h2 = fmaxf(av.z + bv.z, 0.f);
            float h3 = fmaxf(av.w + bv.w, 0.f);
            uint32_t hp0 = pack_bf16x2(h0, h1);
            uint32_t hp1 = pack_bf16x2(h2, h3);
            float e0 = bf16x2_lo_f(hp0), e1 = bf16x2_hi_f(hp0);
            float e2 = bf16x2_lo_f(hp1), e3 = bf16x2_hi_f(hp1);
            uint2 hi = {hp0, hp1};
            uint2 lo = {pack_bf16x2(h0 - e0, h1 - e1),
                        pack_bf16x2(h2 - e2, h3 - e3)};
            *(uint2*)(smem + H_HI + (size_t)r * 144 + (size_t)f * 8) = hi;
            *(uint2*)(smem + H_LO + (size_t)r * 144 + (size_t)f * 8) = lo;
        }
        __syncwarp();

        // Mainloop (warp-private H): same-acc reuse distance 8 MMAs
        float acc[2][8][4] = {};
#pragma unroll
        for (int ks = 0; ks < 4; ++ks) {
            uint32_t A0h[4], A1h[4], A0l[4], A1l[4];
            ldsm4(A0h, a0base + H_HI + ks * 32);
            ldsm4(A1h, a1base + H_HI + ks * 32);
            ldsm4(A0l, a0base + H_LO + ks * 32);
            ldsm4(A1l, a1base + H_LO + ks * 32);
#pragma unroll
            for (int half = 0; half < 2; ++half) {
                uint4 wf[4];
#pragma unroll
                for (int q = 0; q < 4; ++q) {
                    int nt = half * 4 + q;
                    wf[q] = *(const uint4*)(smem + WF + ((nt * 4 + ks) * 32 + lane) * 16);
                }
#pragma unroll
                for (int q = 0; q < 4; ++q)
                    mma_bf16(acc[0][half * 4 + q], A0h, wf[q].x, wf[q].y);
#pragma unroll
                for (int q = 0; q < 4; ++q)
                    mma_bf16(acc[1][half * 4 + q], A1h, wf[q].x, wf[q].y);
#pragma unroll
                for (int q = 0; q < 4; ++q)
                    mma_bf16(acc[0][half * 4 + q], A0l, wf[q].x, wf[q].y);
#pragma unroll
                for (int q = 0; q < 4; ++q)
                    mma_bf16(acc[1][half * 4 + q], A1l, wf[q].x, wf[q].y);
#pragma unroll
                for (int q = 0; q < 4; ++q)
                    mma_bf16(acc[0][half * 4 + q], A0h, wf[q].z, wf[q].w);
#pragma unroll
                for (int q = 0; q < 4; ++q)
                    mma_bf16(acc[1][half * 4 + q], A1h, wf[q].z, wf[q].w);
            }
        }

        // Epilogue: max over node's 16 rows, +bias, relu, store
#pragma unroll
        for (int nd = 0; nd < 2; ++nd) {
            int node = base_node + w * 2 + nd;
#pragma unroll
            for (int nt = 0; nt < 8; ++nt) {
                float m0 = fmaxf(acc[nd][nt][0], acc[nd][nt][2]);
                float m1 = fmaxf(acc[nd][nt][1], acc[nd][nt][3]);
#pragma unroll
                for (int s = 4; s <= 16; s <<= 1) {
                    m0 = fmaxf(m0, __shfl_xor_sync(0xffffffffu, m0, s));
                    m1 = fmaxf(m1, __shfl_xor_sync(0xffffffffu, m1, s));
                }
                if (lane < 4) {
                    int col = nt * 8 + 2 * lane;
                    float2 o;
                    o.x = fmaxf(m0 + __ldg(&b2[col]), 0.f);
                    o.y = fmaxf(m1 + __ldg(&b2[col + 1]), 0.f);
                    *(float2*)(outp + node * 64 + col) = o;
                }
            }
        }
        __syncwarp();   // H reuse safety before next tile's build
    }
}

// ---------------------------------------------------------------------------
// Output layer: one warp per node. out[i] = max_e( relu(A+B) @ Wo2 ) + bo2
__global__ __launch_bounds__(256) void k_out(const float* __restrict__ Wo2,
                                             const float* __restrict__ bo2,
                                             float* __restrict__ out) {
    int warp = (blockIdx.x * blockDim.x + threadIdx.x) >> 5;
    int lane = threadIdx.x & 31;
    if (warp >= NN) return;
    float a0 = g_A[warp * 64 + lane];
    float a1 = g_A[warp * 64 + 32 + lane];
    float w0 = Wo2[lane], w1 = Wo2[32 + lane];
    const int* sp = g_src + warp * DEG;
    float best = -CUDART_INF_F;
#pragma unroll
    for (int e = 0; e < DEG; ++e) {
        int j = sp[e];
        float b0 = g_B[j * 64 + lane];
        float b1 = g_B[j * 64 + 32 + lane];
        float s = fmaxf(a0 + b0, 0.f) * w0 + fmaxf(a1 + b1, 0.f) * w1;
#pragma unroll
        for (int o = 16; o; o >>= 1) s += __shfl_xor_sync(0xffffffffu, s, o);
        best = fmaxf(best, s);
    }
    if (lane == 0) out[warp] = best + bo2[0];
}

// ---------------------------------------------------------------------------
extern "C" void kernel_launch(void* const* d_in, const int* in_sizes, int n_in,
                              void* d_out, int out_size) {
    const float*      x    = (const float*)d_in[0];
    const void*       ei   = d_in[1];
    const float*      eatt = (const float*)d_in[2];
    const float*      Wi1  = (const float*)d_in[3];
    const float*      bi1  = (const float*)d_in[4];
    const float*      Wi2  = (const float*)d_in[5];
    const float*      bi2  = (const float*)d_in[6];
    const float*      Wh1  = (const float*)d_in[7];
    const float*      bh1  = (const float*)d_in[8];
    const float*      Wh2  = (const float*)d_in[9];
    const float*      bh2  = (const float*)d_in[10];
    const float*      Wo1  = (const float*)d_in[11];
    const float*      bo1  = (const float*)d_in[12];
    const float*      Wo2  = (const float*)d_in[13];
    const float*      bo2  = (const float*)d_in[14];
    float*            out  = (float*)d_out;

    cudaFuncSetAttribute(k_edge_mma, cudaFuncAttributeMaxDynamicSharedMemorySize,
                         EDGE_SMEM);
    cudaFuncSetAttribute(k_gemm2, cudaFuncAttributeMaxDynamicSharedMemorySize,
                         GEMM_SMEM);

    k_detect<<<1, 1>>>((const int*)ei);
    k_src<<<(EE + 255) / 256, 256>>>(ei);

    // ONE fused fragment prep for all layers (edge + node GEMM weights)
    k_prepall<<<84, 256>>>(Wi2, Wh2, Wh1, Wo1);

    // Input EdgeConv (A/B exact fp32, then tensor edge phase)
    k_input<<<(NN * HID) / 256, 256>>>(x, Wi1, bi1);
    const int EDGE_GRID = NN / (8 * TILES);                 // 1250
    k_edge_mma<<<EDGE_GRID, 128, EDGE_SMEM>>>(/*lsel=*/0, bi2, /*outsel=*/0);

    const int GEMM_GRID = (NN + 64 * GTILES - 1) / (64 * GTILES);  // 261

    // 6 hidden EdgeConvs; ping-pong g_h0/g_h1
    for (int l = 0; l < NLAYERS; ++l) {
        k_gemm2<<<GEMM_GRID, 128, GEMM_SMEM>>>(/*insel=*/l & 1, /*lsel=*/l,
                                               bh1 + l * 64);
        k_edge_mma<<<EDGE_GRID, 128, EDGE_SMEM>>>(/*lsel=*/l + 1, bh2 + l * 64,
                                                  /*outsel=*/(l + 1) & 1);
    }

    // Output EdgeConv
    k_gemm2<<<GEMM_GRID, 128, GEMM_SMEM>>>(/*insel=*/0, /*lsel=*/6, bo1);
    k_out<<<(NN * 32 + 255) / 256, 256>>>(Wo2, bo2, out);

    cudaMemcpyAsync(out + NN, eatt, (size_t)EE * sizeof(float),
                    cudaMemcpyDeviceToDevice);
}

// round 12
// speedup vs baseline: 1.0872x; 1.0872x over previous
#include <cuda_runtime.h>
#include <cuda_bf16.h>
#include <math_constants.h>
#include <cstdint>

// Problem constants (fixed by setup_inputs)
#define NN 100000
#define EE 1600000
#define DEG 16
#define HID 64
#define NLAYERS 6
#define TILES 5           // tiles (of 8 nodes) per edge block
#define GTILES 2          // tiles (of 64 nodes) per gemm2 block

// ---------------------------------------------------------------------------
// Device scratch (no allocation allowed)
__device__ __align__(128) float g_A[NN * HID];
__device__ __align__(128) float g_B[NN * HID];
__device__ __align__(128) float g_h0[NN * HID];
__device__ __align__(128) float g_h1[NN * HID];
__device__ __align__(128) int   g_src[EE];
__device__ __align__(128) uint4 g_W2F[7 * 1024];   // edge W2 frags, per layer
__device__ __align__(128) uint4 g_WcF[7 * 2048];   // node Wc frags, per layer
__device__ int g_is64;

// ---------------------------------------------------------------------------
// Warp-MMA helpers (sm_80+/sm_90 instructions; target is plain sm_100)
__device__ __forceinline__ uint32_t smem_u32(const void* p) {
    uint32_t a;
    asm("{ .reg .u64 t; cvta.to.shared.u64 t, %1; cvt.u32.u64 %0, t; }"
        : "=r"(a) : "l"(p));
    return a;
}

__device__ __forceinline__ void mma_bf16(float* d, const uint32_t* a,
                                         uint32_t b0, uint32_t b1) {
    asm volatile(
        "mma.sync.aligned.m16n8k16.row.col.f32.bf16.bf16.f32 "
        "{%0,%1,%2,%3}, {%4,%5,%6,%7}, {%8,%9}, {%0,%1,%2,%3};"
        : "+f"(d[0]), "+f"(d[1]), "+f"(d[2]), "+f"(d[3])
        : "r"(a[0]), "r"(a[1]), "r"(a[2]), "r"(a[3]), "r"(b0), "r"(b1));
}

__device__ __forceinline__ void ldsm4(uint32_t* r, uint32_t addr) {
    asm volatile(
        "ldmatrix.sync.aligned.m8n8.x4.shared.b16 {%0,%1,%2,%3}, [%4];"
        : "=r"(r[0]), "=r"(r[1]), "=r"(r[2]), "=r"(r[3]) : "r"(addr));
}

// Pack two f32 -> bf16x2 (lo half = v0, hi half = v1)
__device__ __forceinline__ uint32_t pack_bf16x2(float v0, float v1) {
    uint32_t r;
    asm("cvt.rn.bf16x2.f32 %0, %1, %2;" : "=r"(r) : "f"(v1), "f"(v0));
    return r;
}
__device__ __forceinline__ float bf16_hi_f(float v) {
    __nv_bfloat16 h = __float2bfloat16_rn(v);
    return __bfloat162float(h);
}
// Recover rounded fp32 values from a packed bf16x2 (lo elem / hi elem)
__device__ __forceinline__ float bf16x2_lo_f(uint32_t p) {
    return __uint_as_float(p << 16);
}
__device__ __forceinline__ float bf16x2_hi_f(uint32_t p) {
    return __uint_as_float(p & 0xFFFF0000u);
}

// ---------------------------------------------------------------------------
// Detect int64 vs int32 edge_index (JAX x64-off gives int32)
__global__ void k_detect(const int* __restrict__ ei32) {
    int flag = 1;
    for (int i = 0; i < 64; ++i)
        if (ei32[2 * i + 1] != 0) { flag = 0; break; }
    g_is64 = flag;
}

__global__ void k_src(const void* __restrict__ ei) {
    int e = blockIdx.x * blockDim.x + threadIdx.x;
    if (e >= EE) return;
    if (g_is64) g_src[e] = (int)((const long long*)ei)[e];
    else        g_src[e] = ((const int*)ei)[e];
}

// ---------------------------------------------------------------------------
// Fragment prep helpers (B-fragment layout for m16n8k16; see k_input tail)
__device__ __forceinline__ float wc_elem(const float* W1, int k, int c) {
    return (c < 64) ? W1[k * 64 + c] - W1[(64 + k) * 64 + c]
                    : W1[(64 + k) * 64 + (c - 64)];
}

// ---------------------------------------------------------------------------
// Fused kernel: input-layer A/B (blocks < 25000) + ALL weight-fragment prep
// (tail blocks). Keeps k_edge_mma as the 4th launch for ncu visibility.
#define IN_BLOCKS 25000

__global__ void k_input(const float* __restrict__ x,
                        const float* __restrict__ Wi1,
                        const float* __restrict__ bi1,
                        const float* __restrict__ Wi2,
                        const float* __restrict__ Wh2,
                        const float* __restrict__ Wh1,
                        const float* __restrict__ Wo1) {
    if (blockIdx.x >= IN_BLOCKS) {
        int idx = (blockIdx.x - IN_BLOCKS) * 256 + threadIdx.x;
        if (idx < 7 * 1024) {
            // Edge W2 fragments: layer l (0=input, 1..6=hidden)
            int l = idx >> 10, id = idx & 1023;
            const float* W2 = (l == 0) ? Wi2 : Wh2 + (l - 1) * 4096;
            int fl = id & 31, frag = id >> 5;
            int ks = frag & 3, nt = frag >> 2;
            int kr = ks * 16 + 2 * (fl & 3);
            int nc = nt * 8 + (fl >> 2);
            float v00 = W2[kr * 64 + nc],       v01 = W2[(kr + 1) * 64 + nc];
            float v10 = W2[(kr + 8) * 64 + nc], v11 = W2[(kr + 9) * 64 + nc];
            float h00 = bf16_hi_f(v00), h01 = bf16_hi_f(v01);
            float h10 = bf16_hi_f(v10), h11 = bf16_hi_f(v11);
            uint4 o;
            o.x = pack_bf16x2(h00, h01);
            o.y = pack_bf16x2(h10, h11);
            o.z = pack_bf16x2(v00 - h00, v01 - h01);
            o.w = pack_bf16x2(v10 - h10, v11 - h11);
            g_W2F[idx] = o;
        } else {
            int j = idx - 7 * 1024;
            if (j >= 7 * 2048) return;
            // Node Wc fragments: layer l (0..5 hidden, 6 = output Wo1)
            int l = j >> 11, id = j & 2047;
            const float* W1 = (l < 6) ? Wh1 + l * 8192 : Wo1;
            int fl = id & 31, frag = id >> 5;
            int ks = frag & 3, nt = frag >> 2;            // nt 0..15
            int kr = ks * 16 + 2 * (fl & 3);
            int nc = nt * 8 + (fl >> 2);
            float v00 = wc_elem(W1, kr, nc),     v01 = wc_elem(W1, kr + 1, nc);
            float v10 = wc_elem(W1, kr + 8, nc), v11 = wc_elem(W1, kr + 9, nc);
            float h00 = bf16_hi_f(v00), h01 = bf16_hi_f(v01);
            float h10 = bf16_hi_f(v10), h11 = bf16_hi_f(v11);
            uint4 o;
            o.x = pack_bf16x2(h00, h01);
            o.y = pack_bf16x2(h10, h11);
            o.z = pack_bf16x2(v00 - h00, v01 - h01);
            o.w = pack_bf16x2(v10 - h10, v11 - h11);
            g_WcF[j] = o;
        }
        return;
    }

    // Input layer: A = x @ (Wi1[0:4]-Wi1[4:8]) + bi1,  B = x @ Wi1[4:8]
    int gid = blockIdx.x * blockDim.x + threadIdx.x;
    int i = gid >> 6, t = gid & 63;
    float4 xv = ((const float4*)x)[i];
    float xa[4] = {xv.x, xv.y, xv.z, xv.w};
    float a = bi1[t], b = 0.f;
#pragma unroll
    for (int k = 0; k < 4; ++k) {
        float wt = Wi1[k * 64 + t];
        float wb = Wi1[(4 + k) * 64 + t];
        a += xa[k] * (wt - wb);
        b += xa[k] * wb;
    }
    g_A[gid] = a;
    g_B[gid] = b;
}

// ---------------------------------------------------------------------------
// Node GEMM via mma (3xBF16): GTILES tiles of [A|B] (64 rows x 128 cols).
// Wc fragments staged ONCE per block; grid 782 >= chip capacity (592).
#define GH_HI 0u
#define GH_LO 9216u
#define GWF   18432u
#define GEMM_SMEM 51200

__global__ __launch_bounds__(128, 4) void k_gemm2(int insel, int lsel,
                                                  const float* __restrict__ b1) {
    extern __shared__ __align__(128) char smem[];
    uint32_t sb = smem_u32(smem);
    int tid = threadIdx.x, w = tid >> 5, lane = tid & 31;
    const float* hin = insel ? g_h1 : g_h0;
    const uint4* wsrc = g_WcF + lsel * 2048;

    // stage Wc fragments (32 KB) -- the ONLY block-wide sync
#pragma unroll
    for (int i = 0; i < 16; ++i)
        *(uint4*)(smem + GWF + (size_t)(i * 128 + tid) * 16) =
            wsrc[i * 128 + tid];
    __syncthreads();

    uint32_t abase = sb + (uint32_t)(w * 16 + (lane & 15)) * 144
                        + (uint32_t)(lane >> 4) * 16;

#pragma unroll 1
    for (int t = 0; t < GTILES; ++t) {
        int base = (blockIdx.x * GTILES + t) * 64;
        if (base >= NN) break;

        // Warp-local H build: warp w rows [16w, 16w+16), 16 f4-cols each
#pragma unroll
        for (int i = 0; i < 8; ++i) {
            int r = w * 16 + 2 * i + (lane >> 4);
            int f = lane & 15;
            int nl = base + r; if (nl >= NN) nl = NN - 1;
            float4 hv = __ldg(&((const float4*)hin)[nl * 16 + f]);
            uint32_t hp0 = pack_bf16x2(hv.x, hv.y);
            uint32_t hp1 = pack_bf16x2(hv.z, hv.w);
            float e0 = bf16x2_lo_f(hp0), e1 = bf16x2_hi_f(hp0);
            float e2 = bf16x2_lo_f(hp1), e3 = bf16x2_hi_f(hp1);
            uint2 hi = {hp0, hp1};
            uint2 lo = {pack_bf16x2(hv.x - e0, hv.y - e1),
                        pack_bf16x2(hv.z - e2, hv.w - e3)};
            *(uint2*)(smem + GH_HI + (size_t)r * 144 + (size_t)f * 8) = hi;
            *(uint2*)(smem + GH_LO + (size_t)r * 144 + (size_t)f * 8) = lo;
        }
        __syncwarp();

        float acc[16][4] = {};
#pragma unroll
        for (int ks = 0; ks < 4; ++ks) {
            uint32_t Ah[4], Al[4];
            ldsm4(Ah, abase + GH_HI + ks * 32);
            ldsm4(Al, abase + GH_LO + ks * 32);
#pragma unroll
            for (int half = 0; half < 2; ++half) {
                uint4 wf[8];
#pragma unroll
                for (int q = 0; q < 8; ++q) {
                    int nt = half * 8 + q;
                    wf[q] = *(const uint4*)(smem + GWF + ((nt * 4 + ks) * 32 + lane) * 16);
                }
#pragma unroll
                for (int q = 0; q < 8; ++q)
                    mma_bf16(acc[half * 8 + q], Ah, wf[q].x, wf[q].y);
#pragma unroll
                for (int q = 0; q < 8; ++q)
                    mma_bf16(acc[half * 8 + q], Al, wf[q].x, wf[q].y);
#pragma unroll
                for (int q = 0; q < 8; ++q)
                    mma_bf16(acc[half * 8 + q], Ah, wf[q].z, wf[q].w);
            }
        }

        // Epilogue
        int r0 = base + w * 16 + (lane >> 2);
#pragma unroll
        for (int nt = 0; nt < 16; ++nt) {
            int col = nt * 8 + (lane & 3) * 2;
#pragma unroll
            for (int hf = 0; hf < 2; ++hf) {
                int node = r0 + hf * 8;
                if (node < NN) {
                    float vx = acc[nt][2 * hf], vy = acc[nt][2 * hf + 1];
                    if (col < 64) {
                        vx += __ldg(&b1[col]); vy += __ldg(&b1[col + 1]);
                        *(float2*)(g_A + node * 64 + col) = make_float2(vx, vy);
                    } else {
                        *(float2*)(g_B + node * 64 + col - 64) = make_float2(vx, vy);
                    }
                }
            }
        }
        __syncwarp();   // H reuse safety before next tile's build
    }
}

// ---------------------------------------------------------------------------
// Edge kernel: bf16 mma m16n8k16 (3xBF16), barrier-free multi-tile pipeline.
// Block = 128 thr / 4 warps; TILES tiles of 8 nodes (128 edge rows) each.
// A operand hoisted to 2 registers per tile; src via broadcast LDG (as R10).
#define H_HI  0u
#define H_LO  18432u
#define WF    36864u
#define EDGE_SMEM 53248

__global__ __launch_bounds__(128, 4) void k_edge_mma(int lsel,
                                                     const float* __restrict__ b2,
                                                     int outsel) {
    extern __shared__ __align__(128) char smem[];
    uint32_t sb = smem_u32(smem);
    int tid = threadIdx.x, w = tid >> 5, lane = tid & 31;
    const uint4* wsrc = g_W2F + lsel * 1024;
    float* outp = (outsel ? g_h1 : g_h0);

    // stage W2 fragments (16 KB) -- the only block-wide sync
#pragma unroll
    for (int i = 0; i < 8; ++i)
        *(uint4*)(smem + WF + (size_t)(i * 128 + tid) * 16) =
            wsrc[i * 128 + tid];
    __syncthreads();

    uint32_t a_row = (uint32_t)((lane & 15) * 144 + (lane >> 4) * 16);
    uint32_t a0base = sb + (uint32_t)(w * 32) * 144 + a_row;
    uint32_t a1base = a0base + 16 * 144;
    int f = lane & 15;

#pragma unroll 1
    for (int t = 0; t < TILES; ++t) {
        int tile = blockIdx.x * TILES + t;
        int base_node = tile * 8;

        // A operand: only 2 distinct values per thread (node 2w / 2w+1, col f)
        float4 av0 = __ldg(&((const float4*)g_A)[(base_node + 2 * w) * 16 + f]);
        float4 av1 = __ldg(&((const float4*)g_A)[(base_node + 2 * w + 1) * 16 + f]);

        // H1 build (warp-private rows): h = relu(A + B[src]) hi/lo bf16
#pragma unroll
        for (int i = 0; i < 16; ++i) {
            int r = w * 32 + 2 * i + (lane >> 4);
            int src = __ldg(&g_src[tile * 128 + r]);
            float4 bv = __ldg(&((const float4*)g_B)[src * 16 + f]);
            float4 av = (i < 8) ? av0 : av1;          // node_l = 2w + (i>>3)
            float h0 = fmaxf(av.x + bv.x, 0.f);
            float h1 = fmaxf(av.y + bv.y, 0.f);
            float h2 = fmaxf(av.z + bv.z, 0.f);
            float h3 = fmaxf(av.w + bv.w, 0.f);
            uint32_t hp0 = pack_bf16x2(h0, h1);
            uint32_t hp1 = pack_bf16x2(h2, h3);
            float e0 = bf16x2_lo_f(hp0), e1 = bf16x2_hi_f(hp0);
            float e2 = bf16x2_lo_f(hp1), e3 = bf16x2_hi_f(hp1);
            uint2 hi = {hp0, hp1};
            uint2 lo = {pack_bf16x2(h0 - e0, h1 - e1),
                        pack_bf16x2(h2 - e2, h3 - e3)};
            *(uint2*)(smem + H_HI + (size_t)r * 144 + (size_t)f * 8) = hi;
            *(uint2*)(smem + H_LO + (size_t)r * 144 + (size_t)f * 8) = lo;
        }
        __syncwarp();

        // Mainloop (warp-private H): same-acc reuse distance 8 MMAs
        float acc[2][8][4] = {};
#pragma unroll
        for (int ks = 0; ks < 4; ++ks) {
            uint32_t A0h[4], A1h[4], A0l[4], A1l[4];
            ldsm4(A0h, a0base + H_HI + ks * 32);
            ldsm4(A1h, a1base + H_HI + ks * 32);
            ldsm4(A0l, a0base + H_LO + ks * 32);
            ldsm4(A1l, a1base + H_LO + ks * 32);
#pragma unroll
            for (int half = 0; half < 2; ++half) {
                uint4 wf[4];
#pragma unroll
                for (int q = 0; q < 4; ++q) {
                    int nt = half * 4 + q;
                    wf[q] = *(const uint4*)(smem + WF + ((nt * 4 + ks) * 32 + lane) * 16);
                }
#pragma unroll
                for (int q = 0; q < 4; ++q)
                    mma_bf16(acc[0][half * 4 + q], A0h, wf[q].x, wf[q].y);
#pragma unroll
                for (int q = 0; q < 4; ++q)
                    mma_bf16(acc[1][half * 4 + q], A1h, wf[q].x, wf[q].y);
#pragma unroll
                for (int q = 0; q < 4; ++q)
                    mma_bf16(acc[0][half * 4 + q], A0l, wf[q].x, wf[q].y);
#pragma unroll
                for (int q = 0; q < 4; ++q)
                    mma_bf16(acc[1][half * 4 + q], A1l, wf[q].x, wf[q].y);
#pragma unroll
                for (int q = 0; q < 4; ++q)
                    mma_bf16(acc[0][half * 4 + q], A0h, wf[q].z, wf[q].w);
#pragma unroll
                for (int q = 0; q < 4; ++q)
                    mma_bf16(acc[1][half * 4 + q], A1h, wf[q].z, wf[q].w);
            }
        }

        // Epilogue: max over node's 16 rows, +bias, relu, store
#pragma unroll
        for (int nd = 0; nd < 2; ++nd) {
            int node = base_node + w * 2 + nd;
#pragma unroll
            for (int nt = 0; nt < 8; ++nt) {
                float m0 = fmaxf(acc[nd][nt][0], acc[nd][nt][2]);
                float m1 = fmaxf(acc[nd][nt][1], acc[nd][nt][3]);
#pragma unroll
                for (int s = 4; s <= 16; s <<= 1) {
                    m0 = fmaxf(m0, __shfl_xor_sync(0xffffffffu, m0, s));
                    m1 = fmaxf(m1, __shfl_xor_sync(0xffffffffu, m1, s));
                }
                if (lane < 4) {
                    int col = nt * 8 + 2 * lane;
                    float2 o;
                    o.x = fmaxf(m0 + __ldg(&b2[col]), 0.f);
                    o.y = fmaxf(m1 + __ldg(&b2[col + 1]), 0.f);
                    *(float2*)(outp + node * 64 + col) = o;
                }
            }
        }
        __syncwarp();   // H reuse safety before next tile's build
    }
}

// ---------------------------------------------------------------------------
// Output layer: one warp per node. out[i] = max_e( relu(A+B) @ Wo2 ) + bo2
__global__ __launch_bounds__(256) void k_out(const float* __restrict__ Wo2,
                                             const float* __restrict__ bo2,
                                             float* __restrict__ out) {
    int warp = (blockIdx.x * blockDim.x + threadIdx.x) >> 5;
    int lane = threadIdx.x & 31;
    if (warp >= NN) return;
    float a0 = g_A[warp * 64 + lane];
    float a1 = g_A[warp * 64 + 32 + lane];
    float w0 = Wo2[lane], w1 = Wo2[32 + lane];
    const int* sp = g_src + warp * DEG;
    float best = -CUDART_INF_F;
#pragma unroll
    for (int e = 0; e < DEG; ++e) {
        int j = sp[e];
        float b0 = g_B[j * 64 + lane];
        float b1 = g_B[j * 64 + 32 + lane];
        float s = fmaxf(a0 + b0, 0.f) * w0 + fmaxf(a1 + b1, 0.f) * w1;
#pragma unroll
        for (int o = 16; o; o >>= 1) s += __shfl_xor_sync(0xffffffffu, s, o);
        best = fmaxf(best, s);
    }
    if (lane == 0) out[warp] = best + bo2[0];
}

// ---------------------------------------------------------------------------
extern "C" void kernel_launch(void* const* d_in, const int* in_sizes, int n_in,
                              void* d_out, int out_size) {
    const float*      x    = (const float*)d_in[0];
    const void*       ei   = d_in[1];
    const float*      eatt = (const float*)d_in[2];
    const float*      Wi1  = (const float*)d_in[3];
    const float*      bi1  = (const float*)d_in[4];
    const float*      Wi2  = (const float*)d_in[5];
    const float*      bi2  = (const float*)d_in[6];
    const float*      Wh1  = (const float*)d_in[7];
    const float*      bh1  = (const float*)d_in[8];
    const float*      Wh2  = (const float*)d_in[9];
    const float*      bh2  = (const float*)d_in[10];
    const float*      Wo1  = (const float*)d_in[11];
    const float*      bo1  = (const float*)d_in[12];
    const float*      Wo2  = (const float*)d_in[13];
    const float*      bo2  = (const float*)d_in[14];
    float*            out  = (float*)d_out;

    cudaFuncSetAttribute(k_edge_mma, cudaFuncAttributeMaxDynamicSharedMemorySize,
                         EDGE_SMEM);
    cudaFuncSetAttribute(k_gemm2, cudaFuncAttributeMaxDynamicSharedMemorySize,
                         GEMM_SMEM);

    // Launch order matters for ncu (-s 5 -c 1 captures the 4th launch):
    // 1:detect 2:src 3:input+prep 4:edge  -> edge kernel gets profiled.
    k_detect<<<1, 1>>>((const int*)ei);
    k_src<<<(EE + 255) / 256, 256>>>(ei);
    k_input<<<IN_BLOCKS + 84, 256>>>(x, Wi1, bi1, Wi2, Wh2, Wh1, Wo1);

    const int EDGE_GRID = NN / (8 * TILES);                         // 2500
    k_edge_mma<<<EDGE_GRID, 128, EDGE_SMEM>>>(/*lsel=*/0, bi2, /*outsel=*/0);

    const int GEMM_GRID = (NN + 64 * GTILES - 1) / (64 * GTILES);   // 782

    // 6 hidden EdgeConvs; ping-pong g_h0/g_h1
    for (int l = 0; l < NLAYERS; ++l) {
        k_gemm2<<<GEMM_GRID, 128, GEMM_SMEM>>>(/*insel=*/l & 1, /*lsel=*/l,
                                               bh1 + l * 64);
        k_edge_mma<<<EDGE_GRID, 128, EDGE_SMEM>>>(/*lsel=*/l + 1, bh2 + l * 64,
                                                  /*outsel=*/(l + 1) & 1);
    }

    // Output EdgeConv
    k_gemm2<<<GEMM_GRID, 128, GEMM_SMEM>>>(/*insel=*/0, /*lsel=*/6, bo1);
    k_out<<<(NN * 32 + 255) / 256, 256>>>(Wo2, bo2, out);

    cudaMemcpyAsync(out + NN, eatt, (size_t)EE * sizeof(float),
                    cudaMemcpyDeviceToDevice);
}

// round 13
// speedup vs baseline: 1.1168x; 1.0272x over previous
#include <cuda_runtime.h>
#include <cuda_bf16.h>
#include <math_constants.h>
#include <cstdint>

// Problem constants (fixed by setup_inputs)
#define NN 100000
#define EE 1600000
#define DEG 16
#define HID 64
#define NLAYERS 6
#define TILES 5           // tiles (of 8 nodes) per edge block

// ---------------------------------------------------------------------------
// Device scratch (no allocation allowed)
__device__ __align__(128) float g_A[NN * HID];
__device__ __align__(128) float g_B[NN * HID];
__device__ __align__(128) float g_h0[NN * HID];
__device__ __align__(128) float g_h1[NN * HID];
__device__ __align__(128) int   g_src[EE];
__device__ __align__(128) uint4 g_W2F[7 * 1024];   // edge W2 frags, per layer
__device__ __align__(128) uint4 g_WcF[7 * 2048];   // node Wc frags, per layer
__device__ int g_is64;

// ---------------------------------------------------------------------------
// Warp-MMA helpers (sm_80+/sm_90 instructions; target is plain sm_100)
__device__ __forceinline__ uint32_t smem_u32(const void* p) {
    uint32_t a;
    asm("{ .reg .u64 t; cvta.to.shared.u64 t, %1; cvt.u32.u64 %0, t; }"
        : "=r"(a) : "l"(p));
    return a;
}

__device__ __forceinline__ void mma_bf16(float* d, const uint32_t* a,
                                         uint32_t b0, uint32_t b1) {
    asm volatile(
        "mma.sync.aligned.m16n8k16.row.col.f32.bf16.bf16.f32 "
        "{%0,%1,%2,%3}, {%4,%5,%6,%7}, {%8,%9}, {%0,%1,%2,%3};"
        : "+f"(d[0]), "+f"(d[1]), "+f"(d[2]), "+f"(d[3])
        : "r"(a[0]), "r"(a[1]), "r"(a[2]), "r"(a[3]), "r"(b0), "r"(b1));
}

__device__ __forceinline__ void ldsm4(uint32_t* r, uint32_t addr) {
    asm volatile(
        "ldmatrix.sync.aligned.m8n8.x4.shared.b16 {%0,%1,%2,%3}, [%4];"
        : "=r"(r[0]), "=r"(r[1]), "=r"(r[2]), "=r"(r[3]) : "r"(addr));
}

// Pack two f32 -> bf16x2 (lo half = v0, hi half = v1)
__device__ __forceinline__ uint32_t pack_bf16x2(float v0, float v1) {
    uint32_t r;
    asm("cvt.rn.bf16x2.f32 %0, %1, %2;" : "=r"(r) : "f"(v1), "f"(v0));
    return r;
}
__device__ __forceinline__ float bf16_hi_f(float v) {
    __nv_bfloat16 h = __float2bfloat16_rn(v);
    return __bfloat162float(h);
}
// Recover rounded fp32 values from a packed bf16x2 (lo elem / hi elem)
__device__ __forceinline__ float bf16x2_lo_f(uint32_t p) {
    return __uint_as_float(p << 16);
}
__device__ __forceinline__ float bf16x2_hi_f(uint32_t p) {
    return __uint_as_float(p & 0xFFFF0000u);
}

// ---------------------------------------------------------------------------
// Detect int64 vs int32 edge_index (JAX x64-off gives int32)
__global__ void k_detect(const int* __restrict__ ei32) {
    int flag = 1;
    for (int i = 0; i < 64; ++i)
        if (ei32[2 * i + 1] != 0) { flag = 0; break; }
    g_is64 = flag;
}

__global__ void k_src(const void* __restrict__ ei) {
    int e = blockIdx.x * blockDim.x + threadIdx.x;
    if (e >= EE) return;
    if (g_is64) g_src[e] = (int)((const long long*)ei)[e];
    else        g_src[e] = ((const int*)ei)[e];
}

// ---------------------------------------------------------------------------
// Fragment prep helpers (B-fragment layout for m16n8k16; see k_input tail)
__device__ __forceinline__ float wc_elem(const float* W1, int k, int c) {
    return (c < 64) ? W1[k * 64 + c] - W1[(64 + k) * 64 + c]
                    : W1[(64 + k) * 64 + (c - 64)];
}

// ---------------------------------------------------------------------------
// Fused kernel: input-layer A/B (blocks < 25000) + ALL weight-fragment prep
// (tail blocks). Keeps k_edge_mma as the 4th launch for ncu visibility.
#define IN_BLOCKS 25000

__global__ void k_input(const float* __restrict__ x,
                        const float* __restrict__ Wi1,
                        const float* __restrict__ bi1,
                        const float* __restrict__ Wi2,
                        const float* __restrict__ Wh2,
                        const float* __restrict__ Wh1,
                        const float* __restrict__ Wo1) {
    if (blockIdx.x >= IN_BLOCKS) {
        int idx = (blockIdx.x - IN_BLOCKS) * 256 + threadIdx.x;
        if (idx < 7 * 1024) {
            // Edge W2 fragments: layer l (0=input, 1..6=hidden)
            int l = idx >> 10, id = idx & 1023;
            const float* W2 = (l == 0) ? Wi2 : Wh2 + (l - 1) * 4096;
            int fl = id & 31, frag = id >> 5;
            int ks = frag & 3, nt = frag >> 2;
            int kr = ks * 16 + 2 * (fl & 3);
            int nc = nt * 8 + (fl >> 2);
            float v00 = W2[kr * 64 + nc],       v01 = W2[(kr + 1) * 64 + nc];
            float v10 = W2[(kr + 8) * 64 + nc], v11 = W2[(kr + 9) * 64 + nc];
            float h00 = bf16_hi_f(v00), h01 = bf16_hi_f(v01);
            float h10 = bf16_hi_f(v10), h11 = bf16_hi_f(v11);
            uint4 o;
            o.x = pack_bf16x2(h00, h01);
            o.y = pack_bf16x2(h10, h11);
            o.z = pack_bf16x2(v00 - h00, v01 - h01);
            o.w = pack_bf16x2(v10 - h10, v11 - h11);
            g_W2F[idx] = o;
        } else {
            int j = idx - 7 * 1024;
            if (j >= 7 * 2048) return;
            // Node Wc fragments: layer l (0..5 hidden, 6 = output Wo1)
            int l = j >> 11, id = j & 2047;
            const float* W1 = (l < 6) ? Wh1 + l * 8192 : Wo1;
            int fl = id & 31, frag = id >> 5;
            int ks = frag & 3, nt = frag >> 2;            // nt 0..15
            int kr = ks * 16 + 2 * (fl & 3);
            int nc = nt * 8 + (fl >> 2);
            float v00 = wc_elem(W1, kr, nc),     v01 = wc_elem(W1, kr + 1, nc);
            float v10 = wc_elem(W1, kr + 8, nc), v11 = wc_elem(W1, kr + 9, nc);
            float h00 = bf16_hi_f(v00), h01 = bf16_hi_f(v01);
            float h10 = bf16_hi_f(v10), h11 = bf16_hi_f(v11);
            uint4 o;
            o.x = pack_bf16x2(h00, h01);
            o.y = pack_bf16x2(h10, h11);
            o.z = pack_bf16x2(v00 - h00, v01 - h01);
            o.w = pack_bf16x2(v10 - h10, v11 - h11);
            g_WcF[j] = o;
        }
        return;
    }

    // Input layer: A = x @ (Wi1[0:4]-Wi1[4:8]) + bi1,  B = x @ Wi1[4:8]
    int gid = blockIdx.x * blockDim.x + threadIdx.x;
    int i = gid >> 6, t = gid & 63;
    float4 xv = ((const float4*)x)[i];
    float xa[4] = {xv.x, xv.y, xv.z, xv.w};
    float a = bi1[t], b = 0.f;
#pragma unroll
    for (int k = 0; k < 4; ++k) {
        float wt = Wi1[k * 64 + t];
        float wb = Wi1[(4 + k) * 64 + t];
        a += xa[k] * (wt - wb);
        b += xa[k] * wb;
    }
    g_A[gid] = a;
    g_B[gid] = b;
}

// ---------------------------------------------------------------------------
// Node GEMM via mma (3xBF16), edge-kernel shape: 128-row tile per block,
// warp w owns rows [32w,32w+32) = 2 m16 subtiles; nt in 2 chunks of 8
// (acc stays 64 regs). Fragment-read bytes per row ~halved vs 16-row warps.
#define GH_HI 0u
#define GH_LO 18432u
#define GWF   36864u
#define GEMM_SMEM 69632

__global__ __launch_bounds__(128, 3) void k_gemm2(int insel, int lsel,
                                                  const float* __restrict__ b1) {
    extern __shared__ __align__(128) char smem[];
    uint32_t sb = smem_u32(smem);
    int tid = threadIdx.x, w = tid >> 5, lane = tid & 31;
    int base = blockIdx.x * 128;
    const float* hin = insel ? g_h1 : g_h0;
    const uint4* wsrc = g_WcF + lsel * 2048;

    // stage Wc fragments (32 KB) -- the ONLY block-wide sync
#pragma unroll
    for (int i = 0; i < 16; ++i)
        *(uint4*)(smem + GWF + (size_t)(i * 128 + tid) * 16) =
            wsrc[i * 128 + tid];
    __syncthreads();

    // Warp-local H build: warp w rows [32w, 32w+32), 16 f4-cols each
#pragma unroll
    for (int i = 0; i < 16; ++i) {
        int r = w * 32 + 2 * i + (lane >> 4);
        int f = lane & 15;
        int nl = base + r; if (nl >= NN) nl = NN - 1;
        float4 hv = __ldg(&((const float4*)hin)[nl * 16 + f]);
        uint32_t hp0 = pack_bf16x2(hv.x, hv.y);
        uint32_t hp1 = pack_bf16x2(hv.z, hv.w);
        float e0 = bf16x2_lo_f(hp0), e1 = bf16x2_hi_f(hp0);
        float e2 = bf16x2_lo_f(hp1), e3 = bf16x2_hi_f(hp1);
        uint2 hi = {hp0, hp1};
        uint2 lo = {pack_bf16x2(hv.x - e0, hv.y - e1),
                    pack_bf16x2(hv.z - e2, hv.w - e3)};
        *(uint2*)(smem + GH_HI + (size_t)r * 144 + (size_t)f * 8) = hi;
        *(uint2*)(smem + GH_LO + (size_t)r * 144 + (size_t)f * 8) = lo;
    }
    __syncwarp();

    uint32_t a_row = (uint32_t)((lane & 15) * 144 + (lane >> 4) * 16);
    uint32_t a0base = sb + (uint32_t)(w * 32) * 144 + a_row;
    uint32_t a1base = a0base + 16 * 144;

#pragma unroll 1
    for (int chunk = 0; chunk < 2; ++chunk) {
        float acc[2][8][4] = {};
#pragma unroll
        for (int ks = 0; ks < 4; ++ks) {
            uint32_t A0h[4], A1h[4], A0l[4], A1l[4];
            ldsm4(A0h, a0base + GH_HI + ks * 32);
            ldsm4(A1h, a1base + GH_HI + ks * 32);
            ldsm4(A0l, a0base + GH_LO + ks * 32);
            ldsm4(A1l, a1base + GH_LO + ks * 32);
#pragma unroll
            for (int half = 0; half < 2; ++half) {
                uint4 wf[4];
#pragma unroll
                for (int q = 0; q < 4; ++q) {
                    int nt = chunk * 8 + half * 4 + q;
                    wf[q] = *(const uint4*)(smem + GWF + ((nt * 4 + ks) * 32 + lane) * 16);
                }
#pragma unroll
                for (int q = 0; q < 4; ++q)
                    mma_bf16(acc[0][half * 4 + q], A0h, wf[q].x, wf[q].y);
#pragma unroll
                for (int q = 0; q < 4; ++q)
                    mma_bf16(acc[1][half * 4 + q], A1h, wf[q].x, wf[q].y);
#pragma unroll
                for (int q = 0; q < 4; ++q)
                    mma_bf16(acc[0][half * 4 + q], A0l, wf[q].x, wf[q].y);
#pragma unroll
                for (int q = 0; q < 4; ++q)
                    mma_bf16(acc[1][half * 4 + q], A1l, wf[q].x, wf[q].y);
#pragma unroll
                for (int q = 0; q < 4; ++q)
                    mma_bf16(acc[0][half * 4 + q], A0h, wf[q].z, wf[q].w);
#pragma unroll
                for (int q = 0; q < 4; ++q)
                    mma_bf16(acc[1][half * 4 + q], A1h, wf[q].z, wf[q].w);
            }
        }

        // Chunk epilogue: direct stores, all lanes active
#pragma unroll
        for (int nd = 0; nd < 2; ++nd) {
            int r0 = base + w * 32 + nd * 16 + (lane >> 2);
#pragma unroll
            for (int q = 0; q < 8; ++q) {
                int col = (chunk * 8 + q) * 8 + (lane & 3) * 2;
#pragma unroll
                for (int hf = 0; hf < 2; ++hf) {
                    int node = r0 + hf * 8;
                    if (node < NN) {
                        float vx = acc[nd][q][2 * hf], vy = acc[nd][q][2 * hf + 1];
                        if (col < 64) {
                            vx += __ldg(&b1[col]); vy += __ldg(&b1[col + 1]);
                            *(float2*)(g_A + node * 64 + col) = make_float2(vx, vy);
                        } else {
                            *(float2*)(g_B + node * 64 + col - 64) = make_float2(vx, vy);
                        }
                    }
                }
            }
        }
    }
}

// ---------------------------------------------------------------------------
// Edge kernel: bf16 mma m16n8k16 (3xBF16), barrier-free multi-tile pipeline.
// Block = 128 thr / 4 warps; TILES tiles of 8 nodes (128 edge rows) each.
// Epilogue uses a merge-tree shfl reduction (64 shfls vs 96) with hoisted bias.
#define H_HI  0u
#define H_LO  18432u
#define WF    36864u
#define EDGE_SMEM 53248

__global__ __launch_bounds__(128, 4) void k_edge_mma(int lsel,
                                                     const float* __restrict__ b2,
                                                     int outsel) {
    extern __shared__ __align__(128) char smem[];
    uint32_t sb = smem_u32(smem);
    int tid = threadIdx.x, w = tid >> 5, lane = tid & 31;
    const uint4* wsrc = g_W2F + lsel * 1024;
    float* outp = (outsel ? g_h1 : g_h0);

    // stage W2 fragments (16 KB) -- the only block-wide sync
#pragma unroll
    for (int i = 0; i < 8; ++i)
        *(uint4*)(smem + WF + (size_t)(i * 128 + tid) * 16) =
            wsrc[i * 128 + tid];
    __syncthreads();

    // Hoisted bias: per merge-group p, this lane's two output columns
    float2 bias[4];
#pragma unroll
    for (int p = 0; p < 4; ++p) {
        int col = (2 * p + ((lane >> 2) & 1)) * 8 + 2 * (lane & 3);
        bias[p] = make_float2(__ldg(&b2[col]), __ldg(&b2[col + 1]));
    }

    uint32_t a_row = (uint32_t)((lane & 15) * 144 + (lane >> 4) * 16);
    uint32_t a0base = sb + (uint32_t)(w * 32) * 144 + a_row;
    uint32_t a1base = a0base + 16 * 144;
    int f = lane & 15;

#pragma unroll 1
    for (int t = 0; t < TILES; ++t) {
        int tile = blockIdx.x * TILES + t;
        int base_node = tile * 8;

        // A operand: only 2 distinct values per thread (node 2w / 2w+1, col f)
        float4 av0 = __ldg(&((const float4*)g_A)[(base_node + 2 * w) * 16 + f]);
        float4 av1 = __ldg(&((const float4*)g_A)[(base_node + 2 * w + 1) * 16 + f]);

        // H1 build (warp-private rows): h = relu(A + B[src]) hi/lo bf16
#pragma unroll
        for (int i = 0; i < 16; ++i) {
            int r = w * 32 + 2 * i + (lane >> 4);
            int src = __ldg(&g_src[tile * 128 + r]);
            float4 bv = __ldg(&((const float4*)g_B)[src * 16 + f]);
            float4 av = (i < 8) ? av0 : av1;          // node_l = 2w + (i>>3)
            float h0 = fmaxf(av.x + bv.x, 0.f);
            float h1 = fmaxf(av.y + bv.y, 0.f);
            float h2 = fmaxf(av.z + bv.z, 0.f);
            float h3 = fmaxf(av.w + bv.w, 0.f);
            uint32_t hp0 = pack_bf16x2(h0, h1);
            uint32_t hp1 = pack_bf16x2(h2, h3);
            float e0 = bf16x2_lo_f(hp0), e1 = bf16x2_hi_f(hp0);
            float e2 = bf16x2_lo_f(hp1), e3 = bf16x2_hi_f(hp1);
            uint2 hi = {hp0, hp1};
            uint2 lo = {pack_bf16x2(h0 - e0, h1 - e1),
                        pack_bf16x2(h2 - e2, h3 - e3)};
            *(uint2*)(smem + H_HI + (size_t)r * 144 + (size_t)f * 8) = hi;
            *(uint2*)(smem + H_LO + (size_t)r * 144 + (size_t)f * 8) = lo;
        }
        __syncwarp();

        // Mainloop (warp-private H): same-acc reuse distance 8 MMAs
        float acc[2][8][4] = {};
#pragma unroll
        for (int ks = 0; ks < 4; ++ks) {
            uint32_t A0h[4], A1h[4], A0l[4], A1l[4];
            ldsm4(A0h, a0base + H_HI + ks * 32);
            ldsm4(A1h, a1base + H_HI + ks * 32);
            ldsm4(A0l, a0base + H_LO + ks * 32);
            ldsm4(A1l, a1base + H_LO + ks * 32);
#pragma unroll
            for (int half = 0; half < 2; ++half) {
                uint4 wf[4];
#pragma unroll
                for (int q = 0; q < 4; ++q) {
                    int nt = half * 4 + q;
                    wf[q] = *(const uint4*)(smem + WF + ((nt * 4 + ks) * 32 + lane) * 16);
                }
#pragma unroll
                for (int q = 0; q < 4; ++q)
                    mma_bf16(acc[0][half * 4 + q], A0h, wf[q].x, wf[q].y);
#pragma unroll
                for (int q = 0; q < 4; ++q)
                    mma_bf16(acc[1][half * 4 + q], A1h, wf[q].x, wf[q].y);
#pragma unroll
                for (int q = 0; q < 4; ++q)
                    mma_bf16(acc[0][half * 4 + q], A0l, wf[q].x, wf[q].y);
#pragma unroll
                for (int q = 0; q < 4; ++q)
                    mma_bf16(acc[1][half * 4 + q], A1l, wf[q].x, wf[q].y);
#pragma unroll
                for (int q = 0; q < 4; ++q)
                    mma_bf16(acc[0][half * 4 + q], A0h, wf[q].z, wf[q].w);
#pragma unroll
                for (int q = 0; q < 4; ++q)
                    mma_bf16(acc[1][half * 4 + q], A1h, wf[q].z, wf[q].w);
            }
        }

        // Epilogue: merge-tree max over node's 16 rows, +bias, relu, store.
        // Level s=4 reduces over row-bit2; lanes l and l^4 then hold equal
        // values, so adjacent nt streams are select-merged before s=8,16.
#pragma unroll
        for (int nd = 0; nd < 2; ++nd) {
            int node = base_node + w * 2 + nd;
#pragma unroll
            for (int p = 0; p < 4; ++p) {
                float a0 = fmaxf(acc[nd][2 * p][0],     acc[nd][2 * p][2]);
                float a1 = fmaxf(acc[nd][2 * p][1],     acc[nd][2 * p][3]);
                float b0 = fmaxf(acc[nd][2 * p + 1][0], acc[nd][2 * p + 1][2]);
                float b1 = fmaxf(acc[nd][2 * p + 1][1], acc[nd][2 * p + 1][3]);
                a0 = fmaxf(a0, __shfl_xor_sync(0xffffffffu, a0, 4));
                a1 = fmaxf(a1, __shfl_xor_sync(0xffffffffu, a1, 4));
                b0 = fmaxf(b0, __shfl_xor_sync(0xffffffffu, b0, 4));
                b1 = fmaxf(b1, __shfl_xor_sync(0xffffffffu, b1, 4));
                float c0 = (lane & 4) ? b0 : a0;
                float c1 = (lane & 4) ? b1 : a1;
                c0 = fmaxf(c0, __shfl_xor_sync(0xffffffffu, c0, 8));
                c1 = fmaxf(c1, __shfl_xor_sync(0xffffffffu, c1, 8));
                c0 = fmaxf(c0, __shfl_xor_sync(0xffffffffu, c0, 16));
                c1 = fmaxf(c1, __shfl_xor_sync(0xffffffffu, c1, 16));
                if (lane < 8) {
                    int col = (2 * p + ((lane >> 2) & 1)) * 8 + 2 * (lane & 3);
                    float2 o;
                    o.x = fmaxf(c0 + bias[p].x, 0.f);
                    o.y = fmaxf(c1 + bias[p].y, 0.f);
                    *(float2*)(outp + node * 64 + col) = o;
                }
            }
        }
        // no trailing syncwarp: tile t's ldsm reads retired before epilogue,
        // so tile t+1's STS cannot overtake them within this warp.
    }
}

// ---------------------------------------------------------------------------
// Output layer: one warp per node. out[i] = max_e( relu(A+B) @ Wo2 ) + bo2
__global__ __launch_bounds__(256) void k_out(const float* __restrict__ Wo2,
                                             const float* __restrict__ bo2,
                                             float* __restrict__ out) {
    int warp = (blockIdx.x * blockDim.x + threadIdx.x) >> 5;
    int lane = threadIdx.x & 31;
    if (warp >= NN) return;
    float a0 = g_A[warp * 64 + lane];
    float a1 = g_A[warp * 64 + 32 + lane];
    float w0 = Wo2[lane], w1 = Wo2[32 + lane];
    const int* sp = g_src + warp * DEG;
    float best = -CUDART_INF_F;
#pragma unroll
    for (int e = 0; e < DEG; ++e) {
        int j = sp[e];
        float b0 = g_B[j * 64 + lane];
        float b1 = g_B[j * 64 + 32 + lane];
        float s = fmaxf(a0 + b0, 0.f) * w0 + fmaxf(a1 + b1, 0.f) * w1;
#pragma unroll
        for (int o = 16; o; o >>= 1) s += __shfl_xor_sync(0xffffffffu, s, o);
        best = fmaxf(best, s);
    }
    if (lane == 0) out[warp] = best + bo2[0];
}

// ---------------------------------------------------------------------------
extern "C" void kernel_launch(void* const* d_in, const int* in_sizes, int n_in,
                              void* d_out, int out_size) {
    const float*      x    = (const float*)d_in[0];
    const void*       ei   = d_in[1];
    const float*      eatt = (const float*)d_in[2];
    const float*      Wi1  = (const float*)d_in[3];
    const float*      bi1  = (const float*)d_in[4];
    const float*      Wi2  = (const float*)d_in[5];
    const float*      bi2  = (const float*)d_in[6];
    const float*      Wh1  = (const float*)d_in[7];
    const float*      bh1  = (const float*)d_in[8];
    const float*      Wh2  = (const float*)d_in[9];
    const float*      bh2  = (const float*)d_in[10];
    const float*      Wo1  = (const float*)d_in[11];
    const float*      bo1  = (const float*)d_in[12];
    const float*      Wo2  = (const float*)d_in[13];
    const float*      bo2  = (const float*)d_in[14];
    float*            out  = (float*)d_out;

    cudaFuncSetAttribute(k_edge_mma, cudaFuncAttributeMaxDynamicSharedMemorySize,
                         EDGE_SMEM);
    cudaFuncSetAttribute(k_gemm2, cudaFuncAttributeMaxDynamicSharedMemorySize,
                         GEMM_SMEM);

    // Launch order matters for ncu (-s 5 -c 1 captures the 4th launch):
    // 1:detect 2:src 3:input+prep 4:edge  -> edge kernel gets profiled.
    k_detect<<<1, 1>>>((const int*)ei);
    k_src<<<(EE + 255) / 256, 256>>>(ei);
    k_input<<<IN_BLOCKS + 84, 256>>>(x, Wi1, bi1, Wi2, Wh2, Wh1, Wo1);

    const int EDGE_GRID = NN / (8 * TILES);                 // 2500
    k_edge_mma<<<EDGE_GRID, 128, EDGE_SMEM>>>(/*lsel=*/0, bi2, /*outsel=*/0);

    const int GEMM_GRID = (NN + 127) / 128;                 // 782

    // 6 hidden EdgeConvs; ping-pong g_h0/g_h1
    for (int l = 0; l < NLAYERS; ++l) {
        k_gemm2<<<GEMM_GRID, 128, GEMM_SMEM>>>(/*insel=*/l & 1, /*lsel=*/l,
                                               bh1 + l * 64);
        k_edge_mma<<<EDGE_GRID, 128, EDGE_SMEM>>>(/*lsel=*/l + 1, bh2 + l * 64,
                                                  /*outsel=*/(l + 1) & 1);
    }

    // Output EdgeConv
    k_gemm2<<<GEMM_GRID, 128, GEMM_SMEM>>>(/*insel=*/0, /*lsel=*/6, bo1);
    k_out<<<(NN * 32 + 255) / 256, 256>>>(Wo2, bo2, out);

    cudaMemcpyAsync(out + NN, eatt, (size_t)EE * sizeof(float),
                    cudaMemcpyDeviceToDevice);
}

// round 15
// speedup vs baseline: 1.1485x; 1.0284x over previous
#include <cuda_runtime.h>
#include <cuda_bf16.h>
#include <math_constants.h>
#include <cstdint>

// Problem constants (fixed by setup_inputs)
#define NN 100000
#define EE 1600000
#define DEG 16
#define HID 64
#define NLAYERS 6
#define TILES 5           // tiles (of 8 nodes) per edge block
#define GTILES 2          // tiles (of 64 nodes) per gemm2 block

// ---------------------------------------------------------------------------
// Device scratch (no allocation allowed)
__device__ __align__(128) float g_A[NN * HID];
__device__ __align__(128) float g_B[NN * HID];
__device__ __align__(128) float g_h0[NN * HID];
__device__ __align__(128) float g_h1[NN * HID];
__device__ __align__(128) int   g_src[EE];
__device__ __align__(128) uint4 g_W2F[7 * 1024];   // edge W2 frags, per layer
__device__ __align__(128) uint4 g_WcF[7 * 2048];   // node Wc frags, per layer
__device__ int g_is64;

// ---------------------------------------------------------------------------
// Warp-MMA helpers (sm_80+/sm_90 instructions; target is plain sm_100)
__device__ __forceinline__ uint32_t smem_u32(const void* p) {
    uint32_t a;
    asm("{ .reg .u64 t; cvta.to.shared.u64 t, %1; cvt.u32.u64 %0, t; }"
        : "=r"(a) : "l"(p));
    return a;
}

__device__ __forceinline__ void mma_bf16(float* d, const uint32_t* a,
                                         uint32_t b0, uint32_t b1) {
    asm volatile(
        "mma.sync.aligned.m16n8k16.row.col.f32.bf16.bf16.f32 "
        "{%0,%1,%2,%3}, {%4,%5,%6,%7}, {%8,%9}, {%0,%1,%2,%3};"
        : "+f"(d[0]), "+f"(d[1]), "+f"(d[2]), "+f"(d[3])
        : "r"(a[0]), "r"(a[1]), "r"(a[2]), "r"(a[3]), "r"(b0), "r"(b1));
}

__device__ __forceinline__ void ldsm4(uint32_t* r, uint32_t addr) {
    asm volatile(
        "ldmatrix.sync.aligned.m8n8.x4.shared.b16 {%0,%1,%2,%3}, [%4];"
        : "=r"(r[0]), "=r"(r[1]), "=r"(r[2]), "=r"(r[3]) : "r"(addr));
}

// Pack two f32 -> bf16x2 (lo half = v0, hi half = v1)
__device__ __forceinline__ uint32_t pack_bf16x2(float v0, float v1) {
    uint32_t r;
    asm("cvt.rn.bf16x2.f32 %0, %1, %2;" : "=r"(r) : "f"(v1), "f"(v0));
    return r;
}
__device__ __forceinline__ float bf16_hi_f(float v) {
    __nv_bfloat16 h = __float2bfloat16_rn(v);
    return __bfloat162float(h);
}
// Recover rounded fp32 values from a packed bf16x2 (lo elem / hi elem)
__device__ __forceinline__ float bf16x2_lo_f(uint32_t p) {
    return __uint_as_float(p << 16);
}
__device__ __forceinline__ float bf16x2_hi_f(uint32_t p) {
    return __uint_as_float(p & 0xFFFF0000u);
}

// ---------------------------------------------------------------------------
// Detect int64 vs int32 edge_index (JAX x64-off gives int32)
__global__ void k_detect(const int* __restrict__ ei32) {
    int flag = 1;
    for (int i = 0; i < 64; ++i)
        if (ei32[2 * i + 1] != 0) { flag = 0; break; }
    g_is64 = flag;
}

// src decode + edge_attr passthrough fused (replaces trailing memcpy node)
__global__ void k_src(const void* __restrict__ ei,
                      const float* __restrict__ eatt,
                      float* __restrict__ out) {
    int e = blockIdx.x * blockDim.x + threadIdx.x;
    if (e >= EE) return;
    if (g_is64) g_src[e] = (int)((const long long*)ei)[e];
    else        g_src[e] = ((const int*)ei)[e];
    out[NN + e] = eatt[e];
}

// ---------------------------------------------------------------------------
// Fragment prep helpers (B-fragment layout for m16n8k16; see k_input tail)
__device__ __forceinline__ float wc_elem(const float* W1, int k, int c) {
    return (c < 64) ? W1[k * 64 + c] - W1[(64 + k) * 64 + c]
                    : W1[(64 + k) * 64 + (c - 64)];
}

// ---------------------------------------------------------------------------
// Fused kernel: input-layer A/B (blocks < 25000) + ALL weight-fragment prep
// (tail blocks). Keeps k_edge_mma as the 4th launch for ncu visibility.
#define IN_BLOCKS 25000

__global__ void k_input(const float* __restrict__ x,
                        const float* __restrict__ Wi1,
                        const float* __restrict__ bi1,
                        const float* __restrict__ Wi2,
                        const float* __restrict__ Wh2,
                        const float* __restrict__ Wh1,
                        const float* __restrict__ Wo1) {
    if (blockIdx.x >= IN_BLOCKS) {
        int idx = (blockIdx.x - IN_BLOCKS) * 256 + threadIdx.x;
        if (idx < 7 * 1024) {
            // Edge W2 fragments: layer l (0=input, 1..6=hidden)
            int l = idx >> 10, id = idx & 1023;
            const float* W2 = (l == 0) ? Wi2 : Wh2 + (l - 1) * 4096;
            int fl = id & 31, frag = id >> 5;
            int ks = frag & 3, nt = frag >> 2;
            int kr = ks * 16 + 2 * (fl & 3);
            int nc = nt * 8 + (fl >> 2);
            float v00 = W2[kr * 64 + nc],       v01 = W2[(kr + 1) * 64 + nc];
            float v10 = W2[(kr + 8) * 64 + nc], v11 = W2[(kr + 9) * 64 + nc];
            float h00 = bf16_hi_f(v00), h01 = bf16_hi_f(v01);
            float h10 = bf16_hi_f(v10), h11 = bf16_hi_f(v11);
            uint4 o;
            o.x = pack_bf16x2(h00, h01);
            o.y = pack_bf16x2(h10, h11);
            o.z = pack_bf16x2(v00 - h00, v01 - h01);
            o.w = pack_bf16x2(v10 - h10, v11 - h11);
            g_W2F[idx] = o;
        } else {
            int j = idx - 7 * 1024;
            if (j >= 7 * 2048) return;
            // Node Wc fragments: layer l (0..5 hidden, 6 = output Wo1)
            int l = j >> 11, id = j & 2047;
            const float* W1 = (l < 6) ? Wh1 + l * 8192 : Wo1;
            int fl = id & 31, frag = id >> 5;
            int ks = frag & 3, nt = frag >> 2;            // nt 0..15
            int kr = ks * 16 + 2 * (fl & 3);
            int nc = nt * 8 + (fl >> 2);
            float v00 = wc_elem(W1, kr, nc),     v01 = wc_elem(W1, kr + 1, nc);
            float v10 = wc_elem(W1, kr + 8, nc), v11 = wc_elem(W1, kr + 9, nc);
            float h00 = bf16_hi_f(v00), h01 = bf16_hi_f(v01);
            float h10 = bf16_hi_f(v10), h11 = bf16_hi_f(v11);
            uint4 o;
            o.x = pack_bf16x2(h00, h01);
            o.y = pack_bf16x2(h10, h11);
            o.z = pack_bf16x2(v00 - h00, v01 - h01);
            o.w = pack_bf16x2(v10 - h10, v11 - h11);
            g_WcF[j] = o;
        }
        return;
    }

    // Input layer: A = x @ (Wi1[0:4]-Wi1[4:8]) + bi1,  B = x @ Wi1[4:8]
    int gid = blockIdx.x * blockDim.x + threadIdx.x;
    int i = gid >> 6, t = gid & 63;
    float4 xv = ((const float4*)x)[i];
    float xa[4] = {xv.x, xv.y, xv.z, xv.w};
    float a = bi1[t], b = 0.f;
#pragma unroll
    for (int k = 0; k < 4; ++k) {
        float wt = Wi1[k * 64 + t];
        float wb = Wi1[(4 + k) * 64 + t];
        a += xa[k] * (wt - wb);
        b += xa[k] * wb;
    }
    g_A[gid] = a;
    g_B[gid] = b;
}

// ---------------------------------------------------------------------------
// Node GEMM via mma (3xBF16): GTILES tiles of [A|B] (64 rows x 128 cols).
// R12 configuration (4 blocks/SM, grid 782 >= chip capacity 592).
#define GH_HI 0u
#define GH_LO 9216u
#define GWF   18432u
#define GEMM_SMEM 51200

__global__ __launch_bounds__(128, 4) void k_gemm2(int insel, int lsel,
                                                  const float* __restrict__ b1) {
    extern __shared__ __align__(128) char smem[];
    uint32_t sb = smem_u32(smem);
    int tid = threadIdx.x, w = tid >> 5, lane = tid & 31;
    const float* hin = insel ? g_h1 : g_h0;
    const uint4* wsrc = g_WcF + lsel * 2048;

    // stage Wc fragments (32 KB) -- the ONLY block-wide sync
#pragma unroll
    for (int i = 0; i < 16; ++i)
        *(uint4*)(smem + GWF + (size_t)(i * 128 + tid) * 16) =
            wsrc[i * 128 + tid];
    __syncthreads();

    uint32_t abase = sb + (uint32_t)(w * 16 + (lane & 15)) * 144
                        + (uint32_t)(lane >> 4) * 16;

#pragma unroll 1
    for (int t = 0; t < GTILES; ++t) {
        int base = (blockIdx.x * GTILES + t) * 64;
        if (base >= NN) break;

        // Warp-local H build: warp w rows [16w, 16w+16), 16 f4-cols each
#pragma unroll
        for (int i = 0; i < 8; ++i) {
            int r = w * 16 + 2 * i + (lane >> 4);
            int f = lane & 15;
            int nl = base + r; if (nl >= NN) nl = NN - 1;
            float4 hv = __ldg(&((const float4*)hin)[nl * 16 + f]);
            uint32_t hp0 = pack_bf16x2(hv.x, hv.y);
            uint32_t hp1 = pack_bf16x2(hv.z, hv.w);
            float e0 = bf16x2_lo_f(hp0), e1 = bf16x2_hi_f(hp0);
            float e2 = bf16x2_lo_f(hp1), e3 = bf16x2_hi_f(hp1);
            uint2 hi = {hp0, hp1};
            uint2 lo = {pack_bf16x2(hv.x - e0, hv.y - e1),
                        pack_bf16x2(hv.z - e2, hv.w - e3)};
            *(uint2*)(smem + GH_HI + (size_t)r * 144 + (size_t)f * 8) = hi;
            *(uint2*)(smem + GH_LO + (size_t)r * 144 + (size_t)f * 8) = lo;
        }
        __syncwarp();

        float acc[16][4] = {};
#pragma unroll
        for (int ks = 0; ks < 4; ++ks) {
            uint32_t Ah[4], Al[4];
            ldsm4(Ah, abase + GH_HI + ks * 32);
            ldsm4(Al, abase + GH_LO + ks * 32);
#pragma unroll
            for (int half = 0; half < 2; ++half) {
                uint4 wf[8];
#pragma unroll
                for (int q = 0; q < 8; ++q) {
                    int nt = half * 8 + q;
                    wf[q] = *(const uint4*)(smem + GWF + ((nt * 4 + ks) * 32 + lane) * 16);
                }
#pragma unroll
                for (int q = 0; q < 8; ++q)
                    mma_bf16(acc[half * 8 + q], Ah, wf[q].x, wf[q].y);
#pragma unroll
                for (int q = 0; q < 8; ++q)
                    mma_bf16(acc[half * 8 + q], Al, wf[q].x, wf[q].y);
#pragma unroll
                for (int q = 0; q < 8; ++q)
                    mma_bf16(acc[half * 8 + q], Ah, wf[q].z, wf[q].w);
            }
        }

        // Epilogue
        int r0 = base + w * 16 + (lane >> 2);
#pragma unroll
        for (int nt = 0; nt < 16; ++nt) {
            int col = nt * 8 + (lane & 3) * 2;
#pragma unroll
            for (int hf = 0; hf < 2; ++hf) {
                int node = r0 + hf * 8;
                if (node < NN) {
                    float vx = acc[nt][2 * hf], vy = acc[nt][2 * hf + 1];
                    if (col < 64) {
                        vx += __ldg(&b1[col]); vy += __ldg(&b1[col + 1]);
                        *(float2*)(g_A + node * 64 + col) = make_float2(vx, vy);
                    } else {
                        *(float2*)(g_B + node * 64 + col - 64) = make_float2(vx, vy);
                    }
                }
            }
        }
        __syncwarp();   // H reuse safety before next tile's build
    }
}

// ---------------------------------------------------------------------------
// Edge kernel: bf16 mma m16n8k16 (3xBF16), barrier-free multi-tile pipeline.
// Block = 128 thr / 4 warps; TILES tiles of 8 nodes (128 edge rows) each.
// Epilogue uses a merge-tree shfl reduction (64 shfls) with hoisted bias.
#define H_HI  0u
#define H_LO  18432u
#define WF    36864u
#define EDGE_SMEM 53248

__global__ __launch_bounds__(128, 4) void k_edge_mma(int lsel,
                                                     const float* __restrict__ b2,
                                                     int outsel) {
    extern __shared__ __align__(128) char smem[];
    uint32_t sb = smem_u32(smem);
    int tid = threadIdx.x, w = tid >> 5, lane = tid & 31;
    const uint4* wsrc = g_W2F + lsel * 1024;
    float* outp = (outsel ? g_h1 : g_h0);

    // stage W2 fragments (16 KB) -- the only block-wide sync
#pragma unroll
    for (int i = 0; i < 8; ++i)
        *(uint4*)(smem + WF + (size_t)(i * 128 + tid) * 16) =
            wsrc[i * 128 + tid];
    __syncthreads();

    // Hoisted bias: per merge-group p, this lane's two output columns
    float2 bias[4];
#pragma unroll
    for (int p = 0; p < 4; ++p) {
        int col = (2 * p + ((lane >> 2) & 1)) * 8 + 2 * (lane & 3);
        bias[p] = make_float2(__ldg(&b2[col]), __ldg(&b2[col + 1]));
    }

    uint32_t a_row = (uint32_t)((lane & 15) * 144 + (lane >> 4) * 16);
    uint32_t a0base = sb + (uint32_t)(w * 32) * 144 + a_row;
    uint32_t a1base = a0base + 16 * 144;
    int f = lane & 15;

#pragma unroll 1
    for (int t = 0; t < TILES; ++t) {
        int tile = blockIdx.x * TILES + t;
        int base_node = tile * 8;

        // A operand: only 2 distinct values per thread (node 2w / 2w+1, col f)
        float4 av0 = __ldg(&((const float4*)g_A)[(base_node + 2 * w) * 16 + f]);
        float4 av1 = __ldg(&((const float4*)g_A)[(base_node + 2 * w + 1) * 16 + f]);

        // H1 build (warp-private rows): h = relu(A + B[src]) hi/lo bf16
#pragma unroll
        for (int i = 0; i < 16; ++i) {
            int r = w * 32 + 2 * i + (lane >> 4);
            int src = __ldg(&g_src[tile * 128 + r]);
            float4 bv = __ldg(&((const float4*)g_B)[src * 16 + f]);
            float4 av = (i < 8) ? av0 : av1;          // node_l = 2w + (i>>3)
            float h0 = fmaxf(av.x + bv.x, 0.f);
            float h1 = fmaxf(av.y + bv.y, 0.f);
            float h2 = fmaxf(av.z + bv.z, 0.f);
            float h3 = fmaxf(av.w + bv.w, 0.f);
            uint32_t hp0 = pack_bf16x2(h0, h1);
            uint32_t hp1 = pack_bf16x2(h2, h3);
            float e0 = bf16x2_lo_f(hp0), e1 = bf16x2_hi_f(hp0);
            float e2 = bf16x2_lo_f(hp1), e3 = bf16x2_hi_f(hp1);
            uint2 hi = {hp0, hp1};
            uint2 lo = {pack_bf16x2(h0 - e0, h1 - e1),
                        pack_bf16x2(h2 - e2, h3 - e3)};
            *(uint2*)(smem + H_HI + (size_t)r * 144 + (size_t)f * 8) = hi;
            *(uint2*)(smem + H_LO + (size_t)r * 144 + (size_t)f * 8) = lo;
        }
        __syncwarp();

        // Mainloop (warp-private H): same-acc reuse distance 8 MMAs
        float acc[2][8][4] = {};
#pragma unroll
        for (int ks = 0; ks < 4; ++ks) {
            uint32_t A0h[4], A1h[4], A0l[4], A1l[4];
            ldsm4(A0h, a0base + H_HI + ks * 32);
            ldsm4(A1h, a1base + H_HI + ks * 32);
            ldsm4(A0l, a0base + H_LO + ks * 32);
            ldsm4(A1l, a1base + H_LO + ks * 32);
#pragma unroll
            for (int half = 0; half < 2; ++half) {
                uint4 wf[4];
#pragma unroll
                for (int q = 0; q < 4; ++q) {
                    int nt = half * 4 + q;
                    wf[q] = *(const uint4*)(smem + WF + ((nt * 4 + ks) * 32 + lane) * 16);
                }
#pragma unroll
                for (int q = 0; q < 4; ++q)
                    mma_bf16(acc[0][half * 4 + q], A0h, wf[q].x, wf[q].y);
#pragma unroll
                for (int q = 0; q < 4; ++q)
                    mma_bf16(acc[1][half * 4 + q], A1h, wf[q].x, wf[q].y);
#pragma unroll
                for (int q = 0; q < 4; ++q)
                    mma_bf16(acc[0][half * 4 + q], A0l, wf[q].x, wf[q].y);
#pragma unroll
                for (int q = 0; q < 4; ++q)
                    mma_bf16(acc[1][half * 4 + q], A1l, wf[q].x, wf[q].y);
#pragma unroll
                for (int q = 0; q < 4; ++q)
                    mma_bf16(acc[0][half * 4 + q], A0h, wf[q].z, wf[q].w);
#pragma unroll
                for (int q = 0; q < 4; ++q)
                    mma_bf16(acc[1][half * 4 + q], A1h, wf[q].z, wf[q].w);
            }
        }

        // Epilogue: merge-tree max over node's 16 rows, +bias, relu, store.
#pragma unroll
        for (int nd = 0; nd < 2; ++nd) {
            int node = base_node + w * 2 + nd;
#pragma unroll
            for (int p = 0; p < 4; ++p) {
                float a0 = fmaxf(acc[nd][2 * p][0],     acc[nd][2 * p][2]);
                float a1 = fmaxf(acc[nd][2 * p][1],     acc[nd][2 * p][3]);
                float b0 = fmaxf(acc[nd][2 * p + 1][0], acc[nd][2 * p + 1][2]);
                float b1 = fmaxf(acc[nd][2 * p + 1][1], acc[nd][2 * p + 1][3]);
                a0 = fmaxf(a0, __shfl_xor_sync(0xffffffffu, a0, 4));
                a1 = fmaxf(a1, __shfl_xor_sync(0xffffffffu, a1, 4));
                b0 = fmaxf(b0, __shfl_xor_sync(0xffffffffu, b0, 4));
                b1 = fmaxf(b1, __shfl_xor_sync(0xffffffffu, b1, 4));
                float c0 = (lane & 4) ? b0 : a0;
                float c1 = (lane & 4) ? b1 : a1;
                c0 = fmaxf(c0, __shfl_xor_sync(0xffffffffu, c0, 8));
                c1 = fmaxf(c1, __shfl_xor_sync(0xffffffffu, c1, 8));
                c0 = fmaxf(c0, __shfl_xor_sync(0xffffffffu, c0, 16));
                c1 = fmaxf(c1, __shfl_xor_sync(0xffffffffu, c1, 16));
                if (lane < 8) {
                    int col = (2 * p + ((lane >> 2) & 1)) * 8 + 2 * (lane & 3);
                    float2 o;
                    o.x = fmaxf(c0 + bias[p].x, 0.f);
                    o.y = fmaxf(c1 + bias[p].y, 0.f);
                    *(float2*)(outp + node * 64 + col) = o;
                }
            }
        }
        // no trailing syncwarp: tile t's ldsm reads retired before epilogue,
        // so tile t+1's STS cannot overtake them within this warp.
    }
}

// ---------------------------------------------------------------------------
// Output layer: one warp per node. out[i] = max_e( relu(A+B) @ Wo2 ) + bo2
__global__ __launch_bounds__(256) void k_out(const float* __restrict__ Wo2,
                                             const float* __restrict__ bo2,
                                             float* __restrict__ out) {
    int warp = (blockIdx.x * blockDim.x + threadIdx.x) >> 5;
    int lane = threadIdx.x & 31;
    if (warp >= NN) return;
    float a0 = g_A[warp * 64 + lane];
    float a1 = g_A[warp * 64 + 32 + lane];
    float w0 = Wo2[lane], w1 = Wo2[32 + lane];
    const int* sp = g_src + warp * DEG;
    float best = -CUDART_INF_F;
#pragma unroll
    for (int e = 0; e < DEG; ++e) {
        int j = sp[e];
        float b0 = g_B[j * 64 + lane];
        float b1 = g_B[j * 64 + 32 + lane];
        float s = fmaxf(a0 + b0, 0.f) * w0 + fmaxf(a1 + b1, 0.f) * w1;
#pragma unroll
        for (int o = 16; o; o >>= 1) s += __shfl_xor_sync(0xffffffffu, s, o);
        best = fmaxf(best, s);
    }
    if (lane == 0) out[warp] = best + bo2[0];
}

// ---------------------------------------------------------------------------
extern "C" void kernel_launch(void* const* d_in, const int* in_sizes, int n_in,
                              void* d_out, int out_size) {
    const float*      x    = (const float*)d_in[0];
    const void*       ei   = d_in[1];
    const float*      eatt = (const float*)d_in[2];
    const float*      Wi1  = (const float*)d_in[3];
    const float*      bi1  = (const float*)d_in[4];
    const float*      Wi2  = (const float*)d_in[5];
    const float*      bi2  = (const float*)d_in[6];
    const float*      Wh1  = (const float*)d_in[7];
    const float*      bh1  = (const float*)d_in[8];
    const float*      Wh2  = (const float*)d_in[9];
    const float*      bh2  = (const float*)d_in[10];
    const float*      Wo1  = (const float*)d_in[11];
    const float*      bo1  = (const float*)d_in[12];
    const float*      Wo2  = (const float*)d_in[13];
    const float*      bo2  = (const float*)d_in[14];
    float*            out  = (float*)d_out;

    cudaFuncSetAttribute(k_edge_mma, cudaFuncAttributeMaxDynamicSharedMemorySize,
                         EDGE_SMEM);
    cudaFuncSetAttribute(k_gemm2, cudaFuncAttributeMaxDynamicSharedMemorySize,
                         GEMM_SMEM);

    // Launch order matters for ncu (-s 5 -c 1 captures the 4th launch):
    // 1:detect 2:src(+eatt copy) 3:input+prep 4:edge -> edge gets profiled.
    k_detect<<<1, 1>>>((const int*)ei);
    k_src<<<(EE + 255) / 256, 256>>>(ei, eatt, out);
    k_input<<<IN_BLOCKS + 84, 256>>>(x, Wi1, bi1, Wi2, Wh2, Wh1, Wo1);

    const int EDGE_GRID = NN / (8 * TILES);                         // 2500
    k_edge_mma<<<EDGE_GRID, 128, EDGE_SMEM>>>(/*lsel=*/0, bi2, /*outsel=*/0);

    const int GEMM_GRID = (NN + 64 * GTILES - 1) / (64 * GTILES);   // 782

    // 6 hidden EdgeConvs; ping-pong g_h0/g_h1
    for (int l = 0; l < NLAYERS; ++l) {
        k_gemm2<<<GEMM_GRID, 128, GEMM_SMEM>>>(/*insel=*/l & 1, /*lsel=*/l,
                                               bh1 + l * 64);
        k_edge_mma<<<EDGE_GRID, 128, EDGE_SMEM>>>(/*lsel=*/l + 1, bh2 + l * 64,
                                                  /*outsel=*/(l + 1) & 1);
    }

    // Output EdgeConv
    k_gemm2<<<GEMM_GRID, 128, GEMM_SMEM>>>(/*insel=*/0, /*lsel=*/6, bo1);
    k_out<<<(NN * 32 + 255) / 256, 256>>>(Wo2, bo2, out);
}